// round 3
// baseline (speedup 1.0000x reference)
#include <cuda_runtime.h>
#include <cuda_bf16.h>

#define Bn   8
#define CHn  7
#define Hn   256
#define Wn   256
#define NBR  6
#define C1   64
#define PX   4

// Scratch for the "combined" (B,7,H,W) tensor between the two kernels.
__device__ float g_comb[Bn * CHn * Hn * Wn];

// ---- packed f32x2 helpers ---------------------------------------------------
__device__ __forceinline__ unsigned long long pk2(float lo, float hi) {
    unsigned long long r;
    asm("mov.b64 %0, {%1, %2};" : "=l"(r) : "f"(lo), "f"(hi));
    return r;
}
__device__ __forceinline__ void upk2(unsigned long long v, float& lo, float& hi) {
    asm("mov.b64 {%0, %1}, %2;" : "=f"(lo), "=f"(hi) : "l"(v));
}
__device__ __forceinline__ void fma2(unsigned long long& d,
                                     unsigned long long a, unsigned long long b) {
    asm("fma.rn.f32x2 %0, %1, %2, %0;" : "+l"(d) : "l"(a), "l"(b));
}

// ---------------------------------------------------------------------------
// Kernel 1: one similarity branch per blockIdx.z, packed f32x2 math.
// Smem weights per (c): 9 float4 taps {wb,wb,wc,wc} + 1 float4 {b1,b1,w2,w2}
// (wb = tap on BASE input, wc = tap on CHECK input, pre-swapped per n).
// ---------------------------------------------------------------------------
__global__ __launch_bounds__(256, 2) void branch_kernel(
    const float* __restrict__ x,
    const float* __restrict__ W1, const float* __restrict__ b1,
    const float* __restrict__ W2, const float* __restrict__ b2)
{
    __shared__ float Wp[C1 * 40];   // 10 float4 per channel = 10240 B

    const int tid = threadIdx.y * 64 + threadIdx.x;
    const int n   = blockIdx.z;
    const int base_ic = (n < 3) ? 0 : 1;

    // Stage duplicated weights for this branch.
    for (int i = tid; i < C1 * 9; i += 256) {
        int c = i / 9, k = i % 9;
        float wb = W1[(((n * C1 + c) * 2 + base_ic) * 9) + k];
        float wc = W1[(((n * C1 + c) * 2 + (1 - base_ic)) * 9) + k];
        float* s = &Wp[c * 40 + k * 4];
        s[0] = wb; s[1] = wb; s[2] = wc; s[3] = wc;
    }
    for (int c = tid; c < C1; c += 256) {
        float bv = b1[n * C1 + c], w2v = W2[n * C1 + c];
        float* s = &Wp[c * 40 + 36];
        s[0] = bv; s[1] = bv; s[2] = w2v; s[3] = w2v;
    }
    __syncthreads();

    const int b  = blockIdx.y;
    const int h  = blockIdx.x * 4 + threadIdx.y;
    const int w0 = threadIdx.x * PX;
    const int srcch = (n < 3) ? n : n + 1;

    // Load base + check 3x6 windows (zero-padded), then pack into f32x2 pairs.
    float bw[3][PX + 2], cw[3][PX + 2];
    {
        const float* xb = x + ((size_t)(b * CHn + 3)) * Hn * Wn;
        const float* xc = x + ((size_t)(b * CHn + srcch)) * Hn * Wn;
        #pragma unroll
        for (int r = 0; r < 3; r++) {
            int hh = h - 1 + r;
            bool hok = (hh >= 0) && (hh < Hn);
            #pragma unroll
            for (int c = 0; c < PX + 2; c++) {
                int ww = w0 - 1 + c;
                bool ok = hok && (ww >= 0) && (ww < Wn);
                bw[r][c] = ok ? __ldg(&xb[hh * Wn + ww]) : 0.f;
                cw[r][c] = ok ? __ldg(&xc[hh * Wn + ww]) : 0.f;
            }
        }
    }
    unsigned long long pb[3][5], pc[3][5];
    #pragma unroll
    for (int r = 0; r < 3; r++)
        #pragma unroll
        for (int i = 0; i < 5; i++) {
            pb[r][i] = pk2(bw[r][i], bw[r][i + 1]);
            pc[r][i] = pk2(cw[r][i], cw[r][i + 1]);
        }
    float cen0 = cw[1][1], cen1 = cw[1][2], cen2 = cw[1][3], cen3 = cw[1][4];

    // Base passthrough channel (written once, by z==0 blocks).
    if (n == 0) {
        float4 bc = make_float4(bw[1][1], bw[1][2], bw[1][3], bw[1][4]);
        *(float4*)(g_comb + (((size_t)(b * CHn + 3)) * Hn + h) * Wn + w0) = bc;
    }

    const float bb2 = __ldg(&b2[n]);
    float sim0 = bb2, sim1 = bb2, sim2 = bb2, sim3 = bb2;

    #pragma unroll 2
    for (int c = 0; c < C1; c++) {
        const float4* wq = (const float4*)&Wp[c * 40];
        float4 s9 = wq[9];
        unsigned long long acc01 = pk2(s9.x, s9.y);
        unsigned long long acc23 = acc01;
        const float w2v = s9.z;

        #pragma unroll
        for (int k = 0; k < 9; k++) {
            const int kh = k / 3, kw = k % 3;
            float4 f = wq[k];
            unsigned long long wb2 = pk2(f.x, f.y);
            unsigned long long wc2 = pk2(f.z, f.w);
            fma2(acc01, wb2, pb[kh][kw]);
            fma2(acc23, wb2, pb[kh][kw + 2]);
            fma2(acc01, wc2, pc[kh][kw]);
            fma2(acc23, wc2, pc[kh][kw + 2]);
        }
        float a0, a1, a2, a3;
        upk2(acc01, a0, a1);
        upk2(acc23, a2, a3);
        sim0 = fmaf(w2v, fmaxf(a0, 0.f), sim0);
        sim1 = fmaf(w2v, fmaxf(a1, 0.f), sim1);
        sim2 = fmaf(w2v, fmaxf(a2, 0.f), sim2);
        sim3 = fmaf(w2v, fmaxf(a3, 0.f), sim3);
    }

    float4 outv;
    outv.x = cen0 / (1.f + __expf(-sim0));
    outv.y = cen1 / (1.f + __expf(-sim1));
    outv.z = cen2 / (1.f + __expf(-sim2));
    outv.w = cen3 / (1.f + __expf(-sim3));
    *(float4*)(g_comb + (((size_t)(b * CHn + srcch)) * Hn + h) * Wn + w0) = outv;
}

// ---------------------------------------------------------------------------
// Kernel 2: final 7->7 3x3 SAME conv, packed f32x2.
// Smem weights per (o,ic): 5 float4 = taps (0,1),(2,3),(4,5),(6,7),(8,pad),
// each tap duplicated (w,w).
// ---------------------------------------------------------------------------
__global__ __launch_bounds__(256, 2) void mix_kernel(
    const float* __restrict__ Wm, const float* __restrict__ bm,
    float* __restrict__ out)
{
    __shared__ float Wm2[49 * 20];   // 3920 B
    __shared__ float bms[7];

    const int tid = threadIdx.y * 64 + threadIdx.x;
    for (int i = tid; i < 49 * 9; i += 256) {
        int oc = i / 9, k = i % 9;
        float w = Wm[i];
        Wm2[oc * 20 + k * 2]     = w;
        Wm2[oc * 20 + k * 2 + 1] = w;
        if (k == 8) { Wm2[oc * 20 + 18] = 0.f; Wm2[oc * 20 + 19] = 0.f; }
    }
    if (tid < 7) bms[tid] = bm[tid];
    __syncthreads();

    const int b  = blockIdx.y;
    const int h  = blockIdx.x * 4 + threadIdx.y;
    const int w0 = threadIdx.x * PX;

    unsigned long long acc01[7], acc23[7];
    #pragma unroll
    for (int o = 0; o < 7; o++) {
        unsigned long long bp = pk2(bms[o], bms[o]);
        acc01[o] = bp; acc23[o] = bp;
    }

    #pragma unroll 1
    for (int ic = 0; ic < 7; ic++) {
        const float* xp = g_comb + ((size_t)(b * CHn + ic)) * Hn * Wn;
        float win[3][PX + 2];
        #pragma unroll
        for (int r = 0; r < 3; r++) {
            int hh = h - 1 + r;
            bool hok = (hh >= 0) && (hh < Hn);
            #pragma unroll
            for (int c = 0; c < PX + 2; c++) {
                int ww = w0 - 1 + c;
                win[r][c] = (hok && ww >= 0 && ww < Wn) ? xp[hh * Wn + ww] : 0.f;
            }
        }
        unsigned long long pw[3][5];
        #pragma unroll
        for (int r = 0; r < 3; r++)
            #pragma unroll
            for (int i = 0; i < 5; i++)
                pw[r][i] = pk2(win[r][i], win[r][i + 1]);

        #pragma unroll
        for (int o = 0; o < 7; o++) {
            const float4* wq = (const float4*)&Wm2[(o * 7 + ic) * 20];
            #pragma unroll
            for (int kq = 0; kq < 4; kq++) {
                float4 f = wq[kq];
                unsigned long long wA = pk2(f.x, f.y);
                unsigned long long wB = pk2(f.z, f.w);
                const int kA = 2 * kq, kB = 2 * kq + 1;
                fma2(acc01[o], wA, pw[kA / 3][kA % 3]);
                fma2(acc23[o], wA, pw[kA / 3][kA % 3 + 2]);
                fma2(acc01[o], wB, pw[kB / 3][kB % 3]);
                fma2(acc23[o], wB, pw[kB / 3][kB % 3 + 2]);
            }
            {   // tap k = 8
                float4 f = wq[4];
                unsigned long long wA = pk2(f.x, f.y);
                fma2(acc01[o], wA, pw[2][2]);
                fma2(acc23[o], wA, pw[2][4]);
            }
        }
    }

    #pragma unroll
    for (int o = 0; o < 7; o++) {
        float4 v;
        upk2(acc01[o], v.x, v.y);
        upk2(acc23[o], v.z, v.w);
        *(float4*)(out + (((size_t)(b * CHn + o)) * Hn + h) * Wn + w0) = v;
    }
}

// ---------------------------------------------------------------------------
// kernel_launch: graph-capturable, allocation-free.
// Input order (metadata): x, W1, b1, W2, b2, Wm, bm
// ---------------------------------------------------------------------------
extern "C" void kernel_launch(void* const* d_in, const int* in_sizes, int n_in,
                              void* d_out, int out_size)
{
    const float* x  = (const float*)d_in[0];
    const float* W1 = (const float*)d_in[1];
    const float* b1 = (const float*)d_in[2];
    const float* W2 = (const float*)d_in[3];
    const float* b2 = (const float*)d_in[4];
    const float* Wm = (const float*)d_in[5];
    const float* bm = (const float*)d_in[6];
    float* out = (float*)d_out;

    dim3 block(64, 4, 1);
    dim3 gridB(Hn / 4, Bn, NBR);   // 64 row-tiles, 8 batches, 6 branches
    dim3 gridM(Hn / 4, Bn, 1);

    branch_kernel<<<gridB, block>>>(x, W1, b1, W2, b2);
    mix_kernel<<<gridM, block>>>(Wm, bm, out);
}